// round 4
// baseline (speedup 1.0000x reference)
#include <cuda_runtime.h>

#define BATCH 1024
#define LOG2E 1.4426950408889634f

// ---------------- device scratch (no allocations allowed) ----------------
__device__ float  g_h2[BATCH * 128];   // after layer 2 (pre-BN)
__device__ float  g_sum[128];          // per-col sum of h2 (zeroed by k4 tail)
__device__ float  g_sq[128];           // per-col sum of h2^2
__device__ float4 g_M4[50 * BATCH];    // M[:, f, 0..3] * log2e, f-major
__device__ float  g_M1[50 * BATCH];    // M[:, f, 4]    * log2e, f-major

__device__ __forceinline__ float lrelu(float v) { return fmaxf(v, 0.2f * v); }

// ---- K12: fused  h1 = lrelu(x@W1+b1) ;  h2 = h1@W2+b2  (+ BN partials) ---
// 8 rows per block; h1 lives only in shared memory.
__global__ void __launch_bounds__(256) k12_gemm(const float* __restrict__ x,
                                                const float* __restrict__ W1,
                                                const float* __restrict__ b1,
                                                const float* __restrict__ W2,
                                                const float* __restrict__ b2) {
    __shared__ float xs[8][128];
    __shared__ float h1s[8][256];
    const int t  = threadIdx.x;
    const int r0 = blockIdx.x * 8;

    for (int n = t; n < 8 * 128; n += 256)
        xs[n >> 7][n & 127] = x[(r0 + (n >> 7)) * 128 + (n & 127)];
    __syncthreads();

    // stage 1: thread t owns output column t (of 256)
    {
        float acc[8];
#pragma unroll
        for (int r = 0; r < 8; r++) acc[r] = 0.f;
#pragma unroll 16
        for (int k = 0; k < 128; k++) {
            const float w = W1[k * 256 + t];
#pragma unroll
            for (int r = 0; r < 8; r++) acc[r] = fmaf(xs[r][k], w, acc[r]);
        }
        const float bb = b1[t];
#pragma unroll
        for (int r = 0; r < 8; r++) h1s[r][t] = lrelu(acc[r] + bb);
    }
    __syncthreads();

    // stage 2: 128 cols, 2 row-groups x 4 rows
    {
        const int c  = t & 127;
        const int rg = t >> 7;
        float acc[4];
#pragma unroll
        for (int r = 0; r < 4; r++) acc[r] = 0.f;
#pragma unroll 8
        for (int k = 0; k < 256; k++) {
            const float w = W2[k * 128 + c];
#pragma unroll
            for (int r = 0; r < 4; r++) acc[r] = fmaf(h1s[rg * 4 + r][k], w, acc[r]);
        }
        const float bb = b2[c];
        float s = 0.f, q = 0.f;
#pragma unroll
        for (int r = 0; r < 4; r++) {
            const float v = acc[r] + bb;
            g_h2[(r0 + rg * 4 + r) * 128 + c] = v;
            s += v;
            q = fmaf(v, v, q);
        }
        atomicAdd(&g_sum[c], s);
        atomicAdd(&g_sq[c], q);
    }
}

// ---- K3: BN+lrelu -> layer3 -> attention -> M (pre-scaled) + score base --
__global__ void __launch_bounds__(256) k3_feat(const float* __restrict__ gamma,
                                               const float* __restrict__ beta,
                                               const float* __restrict__ W3,
                                               const float* __restrict__ b3,
                                               const float* __restrict__ Wv,
                                               const float* __restrict__ bv,
                                               const float* __restrict__ Wo,
                                               const float* __restrict__ bo,
                                               const float* __restrict__ T,
                                               const float* __restrict__ Ws,
                                               const float* __restrict__ bs,
                                               float* __restrict__ out) {
    __shared__ float hb[8][128], h3s[8][64], avs[8][64], hhs[8][64];
    __shared__ float Mst[8][250];
    const int t  = threadIdx.x;
    const int r0 = blockIdx.x * 8;

#pragma unroll
    for (int qq = 0; qq < 4; qq++) {
        const int e = t + 256 * qq;
        const int r = e >> 7, c = e & 127;
        const float v   = g_h2[(r0 + r) * 128 + c];
        const float mu  = g_sum[c] * (1.f / BATCH);
        const float var = g_sq[c] * (1.f / BATCH) - mu * mu;
        const float rs  = rsqrtf(var + 1e-5f);
        hb[r][c] = lrelu(fmaf((v - mu) * rs, gamma[c], beta[c]));
    }
    __syncthreads();

    const int c  = t & 63;
    const int rg = t >> 6;               // 4 groups x 2 rows
    {
        float a0 = b3[c], a1 = a0;
#pragma unroll 8
        for (int k = 0; k < 128; k++) {
            const float w = W3[k * 64 + c];
            a0 = fmaf(hb[2 * rg][k], w, a0);
            a1 = fmaf(hb[2 * rg + 1][k], w, a1);
        }
        h3s[2 * rg][c] = lrelu(a0);
        h3s[2 * rg + 1][c] = lrelu(a1);
    }
    __syncthreads();
    {
        float a0 = bv[c], a1 = a0;
#pragma unroll 8
        for (int k = 0; k < 64; k++) {
            const float w = Wv[k * 64 + c];
            a0 = fmaf(h3s[2 * rg][k], w, a0);
            a1 = fmaf(h3s[2 * rg + 1][k], w, a1);
        }
        avs[2 * rg][c] = a0;
        avs[2 * rg + 1][c] = a1;
    }
    __syncthreads();
    {
        float a0 = bo[c] + h3s[2 * rg][c];
        float a1 = bo[c] + h3s[2 * rg + 1][c];
#pragma unroll 8
        for (int k = 0; k < 64; k++) {
            const float w = Wo[k * 64 + c];
            a0 = fmaf(avs[2 * rg][k], w, a0);
            a1 = fmaf(avs[2 * rg + 1][k], w, a1);
        }
        hhs[2 * rg][c] = a0;
        hhs[2 * rg + 1][c] = a1;
    }
    __syncthreads();

    {   // score base: one warp per row
        const int r = t >> 5, l = t & 31;
        float v = hhs[r][l] * Ws[l] + hhs[r][l + 32] * Ws[l + 32];
#pragma unroll
        for (int o = 16; o > 0; o >>= 1) v += __shfl_down_sync(0xffffffffu, v, o);
        if (l == 0) out[r0 + r] = v + bs[0];
    }

    if (t < 250) {                       // M = hh @ T (pre-scaled by log2 e)
        float acc[8];
#pragma unroll
        for (int r = 0; r < 8; r++) acc[r] = 0.f;
#pragma unroll 4
        for (int k = 0; k < 64; k++) {
            const float w = T[k * 250 + t];
#pragma unroll
            for (int r = 0; r < 8; r++) acc[r] = fmaf(hhs[r][k], w, acc[r]);
        }
#pragma unroll
        for (int r = 0; r < 8; r++) Mst[r][t] = acc[r] * LOG2E;
    }
    __syncthreads();

    for (int idx = t; idx < 400; idx += 256) {
        const int r = idx / 50, f = idx % 50;
        g_M4[f * BATCH + r0 + r] = make_float4(Mst[r][5 * f + 0], Mst[r][5 * f + 1],
                                               Mst[r][5 * f + 2], Mst[r][5 * f + 3]);
        g_M1[f * BATCH + r0 + r] = Mst[r][5 * f + 4];
    }
}

// ------- K4: MBD, symmetric pairs, 10 features per block -----------------
// grid (136 upper-tri 64x64 tiles, 5 feature groups), 256 threads (16x16),
// each thread a 4x4 pair sub-tile; weighted feature accumulation in regs;
// ONE reduction + ONE atomic set per block.
__global__ void __launch_bounds__(256) k4_mbd(const float* __restrict__ Ws,
                                              float* __restrict__ out) {
    __shared__ float4 si4[64], sj4[64];
    __shared__ float  si1[64], sj1[64];
    __shared__ float  red[16][132];

    const int t = threadIdx.x;
    int u = blockIdx.x, ti_s = 0;
    while (u >= 16 - ti_s) { u -= 16 - ti_s; ti_s++; }
    const int tj_s = ti_s + u;
    const int I0 = ti_s * 64, J0 = tj_s * 64;
    const bool diag = (ti_s == tj_s);
    const int ti = t >> 4, tj = t & 15;

    float raccW[4] = {0.f, 0.f, 0.f, 0.f};
    float caccW[4] = {0.f, 0.f, 0.f, 0.f};

    for (int ff = 0; ff < 10; ff++) {
        const int f = blockIdx.y * 10 + ff;
        const float4* __restrict__ M4 = g_M4 + f * BATCH;
        const float*  __restrict__ M1 = g_M1 + f * BATCH;
        __syncthreads();                 // prior feature's tile reads done
        if (t < 64)       si4[t]       = M4[I0 + t];
        else if (t < 128) si1[t - 64]  = M1[I0 + t - 64];
        else if (t < 192) sj4[t - 128] = M4[J0 + t - 128];
        else              sj1[t - 192] = M1[J0 + t - 192];
        __syncthreads();

        float4 mi4[4], mj4[4];
        float  mi1[4], mj1[4];
#pragma unroll
        for (int a = 0; a < 4; a++) {
            mi4[a] = si4[ti * 4 + a]; mi1[a] = si1[ti * 4 + a];
            mj4[a] = sj4[tj * 4 + a]; mj1[a] = sj1[tj * 4 + a];
        }

        float racc[4] = {0.f, 0.f, 0.f, 0.f};
        float cacc[4] = {0.f, 0.f, 0.f, 0.f};
#pragma unroll
        for (int a = 0; a < 4; a++) {
#pragma unroll
            for (int b = 0; b < 4; b++) {
                const float4 A = mi4[a], B = mj4[b];
                float nd = -fabsf(A.x - B.x) - fabsf(A.y - B.y);
                nd = nd - fabsf(A.z - B.z) - fabsf(A.w - B.w);
                nd = nd - fabsf(mi1[a] - mj1[b]);   // already log2e-scaled
                if (!diag || (ti * 4 + a) > (tj * 4 + b)) {
                    float e;
                    asm("ex2.approx.f32 %0, %1;" : "=f"(e) : "f"(nd));
                    racc[a] += e;
                    cacc[b] += e;
                }
            }
        }
        const float wf = Ws[64 + f];
#pragma unroll
        for (int a = 0; a < 4; a++) {
            raccW[a] = fmaf(racc[a], wf, raccW[a]);
            caccW[a] = fmaf(cacc[a], wf, caccW[a]);
        }
    }

    __syncthreads();
#pragma unroll
    for (int a = 0; a < 4; a++) red[tj][ti * 4 + a] = raccW[a];
#pragma unroll
    for (int b = 0; b < 4; b++) red[ti][64 + tj * 4 + b] = caccW[b];
    __syncthreads();

    if (t < 128) {
        float s = 0.f;
#pragma unroll
        for (int g = 0; g < 16; g++) s += red[g][t];
        const int target = (t < 64) ? (I0 + t) : (J0 + t - 64);
        atomicAdd(&out[target], s);
    }

    // re-zero BN stat accumulators for the NEXT graph replay (k4 is the
    // final node; next replay's k12 depends on it via stream order).
    if (blockIdx.x == 0 && blockIdx.y == 0 && t < 128) {
        g_sum[t] = 0.f;
        g_sq[t]  = 0.f;
    }
}

// ---------------- launcher ----------------
extern "C" void kernel_launch(void* const* d_in, const int* in_sizes, int n_in,
                              void* d_out, int out_size) {
    const float* x     = (const float*)d_in[0];
    const float* W1    = (const float*)d_in[1];
    const float* b1    = (const float*)d_in[2];
    const float* W2    = (const float*)d_in[3];
    const float* b2    = (const float*)d_in[4];
    const float* gamma = (const float*)d_in[5];
    const float* beta  = (const float*)d_in[6];
    const float* W3    = (const float*)d_in[7];
    const float* b3    = (const float*)d_in[8];
    const float* Wv    = (const float*)d_in[9];
    const float* bv    = (const float*)d_in[10];
    const float* Wo    = (const float*)d_in[11];
    const float* bo    = (const float*)d_in[12];
    const float* T     = (const float*)d_in[13];
    const float* Ws    = (const float*)d_in[14];
    const float* bs    = (const float*)d_in[15];
    float* out = (float*)d_out;

    k12_gemm<<<128, 256>>>(x, W1, b1, W2, b2);
    k3_feat<<<128, 256>>>(gamma, beta, W3, b3, Wv, bv, Wo, bo, T, Ws, bs, out);
    k4_mbd<<<dim3(136, 5), 256>>>(Ws, out);
}

// round 5
// speedup vs baseline: 1.1231x; 1.1231x over previous
#include <cuda_runtime.h>

#define BATCH 1024
#define LOG2E 1.4426950408889634f

// ---------------- device scratch (no allocations allowed) ----------------
__device__ float  g_h2[BATCH * 128];   // after layer 2 (pre-BN)
__device__ float  g_sum[128];          // per-col sum of h2 (zeroed by k4 tail)
__device__ float  g_sq[128];           // per-col sum of h2^2
__device__ float4 g_M4[50 * BATCH];    // M[:, f, 0..3] * log2e, f-major
__device__ float  g_M1[50 * BATCH];    // M[:, f, 4]    * log2e, f-major

__device__ __forceinline__ float lrelu(float v) { return fmaxf(v, 0.2f * v); }

// ---- K12: fused  h1 = lrelu(x@W1+b1) ;  h2 = h1@W2+b2  (+ BN partials) ---
// 8 rows per block, 512 threads (16 warps/SM -> latency cover), h1 in smem.
__global__ void __launch_bounds__(512) k12_gemm(const float* __restrict__ x,
                                                const float* __restrict__ W1,
                                                const float* __restrict__ b1,
                                                const float* __restrict__ W2,
                                                const float* __restrict__ b2) {
    __shared__ float xs[8][128];
    __shared__ float h1s[8][256];
    const int t  = threadIdx.x;
    const int r0 = blockIdx.x * 8;

    for (int n = t; n < 8 * 128; n += 512)
        xs[n >> 7][n & 127] = x[(r0 + (n >> 7)) * 128 + (n & 127)];
    __syncthreads();

    // stage 1: 256 cols x 2 row-groups (4 rows each)
    {
        const int c = t & 255, g = t >> 8;
        float acc[4] = {0.f, 0.f, 0.f, 0.f};
#pragma unroll 16
        for (int k = 0; k < 128; k++) {
            const float w = W1[k * 256 + c];
#pragma unroll
            for (int r = 0; r < 4; r++) acc[r] = fmaf(xs[g * 4 + r][k], w, acc[r]);
        }
        const float bb = b1[c];
#pragma unroll
        for (int r = 0; r < 4; r++) h1s[g * 4 + r][c] = lrelu(acc[r] + bb);
    }
    __syncthreads();

    // stage 2: 128 cols x 4 row-groups (2 rows each)
    {
        const int c = t & 127, g = t >> 7;
        float a0 = 0.f, a1 = 0.f;
#pragma unroll 16
        for (int k = 0; k < 256; k++) {
            const float w = W2[k * 128 + c];
            a0 = fmaf(h1s[g * 2][k], w, a0);
            a1 = fmaf(h1s[g * 2 + 1][k], w, a1);
        }
        const float bb = b2[c];
        const float v0 = a0 + bb, v1 = a1 + bb;
        g_h2[(r0 + g * 2) * 128 + c]     = v0;
        g_h2[(r0 + g * 2 + 1) * 128 + c] = v1;
        atomicAdd(&g_sum[c], v0 + v1);
        atomicAdd(&g_sq[c], fmaf(v0, v0, v1 * v1));
    }
}

// ---- K3: BN+lrelu -> layer3 -> attention -> M (pre-scaled) + score base --
__global__ void __launch_bounds__(256) k3_feat(const float* __restrict__ gamma,
                                               const float* __restrict__ beta,
                                               const float* __restrict__ W3,
                                               const float* __restrict__ b3,
                                               const float* __restrict__ Wv,
                                               const float* __restrict__ bv,
                                               const float* __restrict__ Wo,
                                               const float* __restrict__ bo,
                                               const float* __restrict__ T,
                                               const float* __restrict__ Ws,
                                               const float* __restrict__ bs,
                                               float* __restrict__ out) {
    __shared__ float hb[8][128], h3s[8][64], avs[8][64], hhs[8][64];
    __shared__ float Mst[8][250];
    const int t  = threadIdx.x;
    const int r0 = blockIdx.x * 8;

#pragma unroll
    for (int qq = 0; qq < 4; qq++) {
        const int e = t + 256 * qq;
        const int r = e >> 7, c = e & 127;
        const float v   = g_h2[(r0 + r) * 128 + c];
        const float mu  = g_sum[c] * (1.f / BATCH);
        const float var = g_sq[c] * (1.f / BATCH) - mu * mu;
        const float rs  = rsqrtf(var + 1e-5f);
        hb[r][c] = lrelu(fmaf((v - mu) * rs, gamma[c], beta[c]));
    }
    __syncthreads();

    const int c  = t & 63;
    const int rg = t >> 6;               // 4 groups x 2 rows
    {
        float a0 = b3[c], a1 = a0;
#pragma unroll 8
        for (int k = 0; k < 128; k++) {
            const float w = W3[k * 64 + c];
            a0 = fmaf(hb[2 * rg][k], w, a0);
            a1 = fmaf(hb[2 * rg + 1][k], w, a1);
        }
        h3s[2 * rg][c] = lrelu(a0);
        h3s[2 * rg + 1][c] = lrelu(a1);
    }
    __syncthreads();
    {
        float a0 = bv[c], a1 = a0;
#pragma unroll 8
        for (int k = 0; k < 64; k++) {
            const float w = Wv[k * 64 + c];
            a0 = fmaf(h3s[2 * rg][k], w, a0);
            a1 = fmaf(h3s[2 * rg + 1][k], w, a1);
        }
        avs[2 * rg][c] = a0;
        avs[2 * rg + 1][c] = a1;
    }
    __syncthreads();
    {
        float a0 = bo[c] + h3s[2 * rg][c];
        float a1 = bo[c] + h3s[2 * rg + 1][c];
#pragma unroll 8
        for (int k = 0; k < 64; k++) {
            const float w = Wo[k * 64 + c];
            a0 = fmaf(avs[2 * rg][k], w, a0);
            a1 = fmaf(avs[2 * rg + 1][k], w, a1);
        }
        hhs[2 * rg][c] = a0;
        hhs[2 * rg + 1][c] = a1;
    }
    __syncthreads();

    {   // score base: one warp per row
        const int r = t >> 5, l = t & 31;
        float v = hhs[r][l] * Ws[l] + hhs[r][l + 32] * Ws[l + 32];
#pragma unroll
        for (int o = 16; o > 0; o >>= 1) v += __shfl_down_sync(0xffffffffu, v, o);
        if (l == 0) out[r0 + r] = v + bs[0];
    }

    if (t < 250) {                       // M = hh @ T (pre-scaled by log2 e)
        float acc[8];
#pragma unroll
        for (int r = 0; r < 8; r++) acc[r] = 0.f;
#pragma unroll 4
        for (int k = 0; k < 64; k++) {
            const float w = T[k * 250 + t];
#pragma unroll
            for (int r = 0; r < 8; r++) acc[r] = fmaf(hhs[r][k], w, acc[r]);
        }
#pragma unroll
        for (int r = 0; r < 8; r++) Mst[r][t] = acc[r] * LOG2E;
    }
    __syncthreads();

    for (int idx = t; idx < 400; idx += 256) {
        const int r = idx / 50, f = idx % 50;
        g_M4[f * BATCH + r0 + r] = make_float4(Mst[r][5 * f + 0], Mst[r][5 * f + 1],
                                               Mst[r][5 * f + 2], Mst[r][5 * f + 3]);
        g_M1[f * BATCH + r0 + r] = Mst[r][5 * f + 4];
    }
}

// ------- K4: MBD, symmetric pairs, 10 features per block -----------------
// All 10 features' 64-row tiles preloaded to smem once (one sync).
// 256 threads (16x16), each a 4x4 pair sub-tile; diag branch specialized.
__global__ void __launch_bounds__(256) k4_mbd(const float* __restrict__ Ws,
                                              float* __restrict__ out) {
    __shared__ float4 si4[10][64], sj4[10][64];
    __shared__ float  si1[10][64], sj1[10][64];
    __shared__ float  red[16][132];

    const int t = threadIdx.x;
    int u = blockIdx.x, ti_s = 0;
    while (u >= 16 - ti_s) { u -= 16 - ti_s; ti_s++; }
    const int tj_s = ti_s + u;
    const int I0 = ti_s * 64, J0 = tj_s * 64;
    const bool diag = (ti_s == tj_s);
    const int ti = t >> 4, tj = t & 15;

    const float4* __restrict__ M4 = g_M4 + blockIdx.y * 10 * BATCH;
    const float*  __restrict__ M1 = g_M1 + blockIdx.y * 10 * BATCH;
    for (int idx = t; idx < 640; idx += 256) {
        const int ff = idx >> 6, r = idx & 63;
        si4[ff][r] = M4[ff * BATCH + I0 + r];
        sj4[ff][r] = M4[ff * BATCH + J0 + r];
        si1[ff][r] = M1[ff * BATCH + I0 + r];
        sj1[ff][r] = M1[ff * BATCH + J0 + r];
    }
    __syncthreads();

    float raccW[4] = {0.f, 0.f, 0.f, 0.f};
    float caccW[4] = {0.f, 0.f, 0.f, 0.f};

#pragma unroll 1
    for (int ff = 0; ff < 10; ff++) {
        float4 mi4[4], mj4[4];
        float  mi1[4], mj1[4];
#pragma unroll
        for (int a = 0; a < 4; a++) {
            mi4[a] = si4[ff][ti * 4 + a]; mi1[a] = si1[ff][ti * 4 + a];
            mj4[a] = sj4[ff][tj * 4 + a]; mj1[a] = sj1[ff][tj * 4 + a];
        }

        float racc[4] = {0.f, 0.f, 0.f, 0.f};
        float cacc[4] = {0.f, 0.f, 0.f, 0.f};
        if (!diag) {
#pragma unroll
            for (int a = 0; a < 4; a++) {
#pragma unroll
                for (int b = 0; b < 4; b++) {
                    const float4 A = mi4[a], B = mj4[b];
                    float nd = -fabsf(A.x - B.x) - fabsf(A.y - B.y);
                    nd = nd - fabsf(A.z - B.z) - fabsf(A.w - B.w);
                    nd = nd - fabsf(mi1[a] - mj1[b]);
                    float e;
                    asm("ex2.approx.f32 %0, %1;" : "=f"(e) : "f"(nd));
                    racc[a] += e;
                    cacc[b] += e;
                }
            }
        } else {
#pragma unroll
            for (int a = 0; a < 4; a++) {
#pragma unroll
                for (int b = 0; b < 4; b++) {
                    if ((ti * 4 + a) > (tj * 4 + b)) {
                        const float4 A = mi4[a], B = mj4[b];
                        float nd = -fabsf(A.x - B.x) - fabsf(A.y - B.y);
                        nd = nd - fabsf(A.z - B.z) - fabsf(A.w - B.w);
                        nd = nd - fabsf(mi1[a] - mj1[b]);
                        float e;
                        asm("ex2.approx.f32 %0, %1;" : "=f"(e) : "f"(nd));
                        racc[a] += e;
                        cacc[b] += e;
                    }
                }
            }
        }
        const float wf = Ws[64 + blockIdx.y * 10 + ff];
#pragma unroll
        for (int a = 0; a < 4; a++) {
            raccW[a] = fmaf(racc[a], wf, raccW[a]);
            caccW[a] = fmaf(cacc[a], wf, caccW[a]);
        }
    }

    __syncthreads();
#pragma unroll
    for (int a = 0; a < 4; a++) red[tj][ti * 4 + a] = raccW[a];
#pragma unroll
    for (int b = 0; b < 4; b++) red[ti][64 + tj * 4 + b] = caccW[b];
    __syncthreads();

    if (t < 128) {
        float s = 0.f;
#pragma unroll
        for (int g = 0; g < 16; g++) s += red[g][t];
        const int target = (t < 64) ? (I0 + t) : (J0 + t - 64);
        atomicAdd(&out[target], s);
    }

    // re-zero BN stat accumulators for the NEXT graph replay (k4 is the
    // final node; next replay's k12 follows it in stream order).
    if (blockIdx.x == 0 && blockIdx.y == 0 && t < 128) {
        g_sum[t] = 0.f;
        g_sq[t]  = 0.f;
    }
}

// ---------------- launcher ----------------
extern "C" void kernel_launch(void* const* d_in, const int* in_sizes, int n_in,
                              void* d_out, int out_size) {
    const float* x     = (const float*)d_in[0];
    const float* W1    = (const float*)d_in[1];
    const float* b1    = (const float*)d_in[2];
    const float* W2    = (const float*)d_in[3];
    const float* b2    = (const float*)d_in[4];
    const float* gamma = (const float*)d_in[5];
    const float* beta  = (const float*)d_in[6];
    const float* W3    = (const float*)d_in[7];
    const float* b3    = (const float*)d_in[8];
    const float* Wv    = (const float*)d_in[9];
    const float* bv    = (const float*)d_in[10];
    const float* Wo    = (const float*)d_in[11];
    const float* bo    = (const float*)d_in[12];
    const float* T     = (const float*)d_in[13];
    const float* Ws    = (const float*)d_in[14];
    const float* bs    = (const float*)d_in[15];
    float* out = (float*)d_out;

    k12_gemm<<<128, 512>>>(x, W1, b1, W2, b2);
    k3_feat<<<128, 256>>>(gamma, beta, W3, b3, Wv, bv, Wo, bo, T, Ws, bs, out);
    k4_mbd<<<dim3(136, 5), 256>>>(Ws, out);
}